// round 10
// baseline (speedup 1.0000x reference)
#include <cuda_runtime.h>
#include <cuda_bf16.h>
#include <cstdint>

// ---------------------------------------------------------------- constants
#define B_Q    256
#define DIM    512
#define N_MEM  500000
#define TOPK   5
#define BN     128
#define KC     64
#define NCH    8                       // 512 / 64
#define NTILE  3907                    // ceil(500000/128)
#define TILE_K 4                       // approx top-k kept per tile
#define GK     20                      // global approx candidates rescored exactly

#define APITCH 528                     // A smem row pitch (512B data + 16 pad)
#define BPITCH 80                      // B smem row pitch (64B data + 16 pad)

// smem layout (bytes)
#define SM_A   0                       // A int8 resident: 256*528 = 135168
#define SM_B   135168                  // B int8 db: 2*128*80 = 20480
#define SM_MS  155648                  // 128 floats ||m||^2
#define SM_SC  156160                  // 128 floats 2*scale_m
#define SMEM_BYTES 156672
// epilogue dist tile (256*129*4 = 132096) overlays [0, 132096) (A region)

// ---------------------------------------------------------------- scratch
__device__ __align__(16) int8_t g_q8[B_Q * DIM];
__device__ __align__(16) int8_t g_m8[(size_t)N_MEM * DIM];
__device__ float g_qs[B_Q];            // query int8 scale
__device__ float g_qsq[B_Q];           // exact ||q||^2
__device__ float g_ms[N_MEM];          // memory int8 scale
__device__ float g_msq[N_MEM];         // exact ||m||^2
__device__ float g_pd[(size_t)B_Q * NTILE * TILE_K];
__device__ int   g_pi[(size_t)B_Q * NTILE * TILE_K];

// ---------------------------------------------------------------- helpers
__device__ __forceinline__ uint32_t smem_u32(const void* p) {
    uint32_t a;
    asm("{ .reg .u64 t; cvta.to.shared.u64 t, %1; cvt.u32.u64 %0, t; }" : "=r"(a) : "l"(p));
    return a;
}
__device__ __forceinline__ void cp16(uint32_t dst, const void* src) {
    asm volatile("cp.async.cg.shared.global [%0], [%1], 16;" :: "r"(dst), "l"(src));
}
#define CP_COMMIT() asm volatile("cp.async.commit_group;" ::: "memory")
#define CP_WAIT0()  asm volatile("cp.async.wait_group 0;" ::: "memory")

__device__ __forceinline__ void ldsm4(uint32_t a, uint32_t& r0, uint32_t& r1,
                                      uint32_t& r2, uint32_t& r3) {
    asm volatile("ldmatrix.sync.aligned.m8n8.x4.shared.b16 {%0,%1,%2,%3}, [%4];"
                 : "=r"(r0), "=r"(r1), "=r"(r2), "=r"(r3) : "r"(a));
}
__device__ __forceinline__ void mma_s8(int* d, const uint32_t* a, const uint32_t* b) {
    asm volatile(
        "mma.sync.aligned.m16n8k32.row.col.s32.s8.s8.s32 "
        "{%0,%1,%2,%3}, {%4,%5,%6,%7}, {%8,%9}, {%0,%1,%2,%3};"
        : "+r"(d[0]), "+r"(d[1]), "+r"(d[2]), "+r"(d[3])
        : "r"(a[0]), "r"(a[1]), "r"(a[2]), "r"(a[3]), "r"(b[0]), "r"(b[1]));
}

// quantize one row (warp-collective): per-row scale, int8 pack, exact sumsq
__device__ __forceinline__ void quant_row(const float4* row, uint32_t* dst8,
                                          float* d_scale, float* d_sumsq, int lane) {
    float4 v[4];
    float mx = 0.f, sq = 0.f;
#pragma unroll
    for (int j = 0; j < 4; j++) {
        v[j] = row[lane + 32 * j];
        mx = fmaxf(mx, fmaxf(fmaxf(fabsf(v[j].x), fabsf(v[j].y)),
                             fmaxf(fabsf(v[j].z), fabsf(v[j].w))));
        sq += v[j].x * v[j].x + v[j].y * v[j].y + v[j].z * v[j].z + v[j].w * v[j].w;
    }
#pragma unroll
    for (int o = 16; o > 0; o >>= 1) {
        mx = fmaxf(mx, __shfl_xor_sync(0xFFFFFFFFu, mx, o));
        sq += __shfl_xor_sync(0xFFFFFFFFu, sq, o);
    }
    float inv = (mx > 0.f) ? (127.0f / mx) : 0.f;
#pragma unroll
    for (int j = 0; j < 4; j++) {
        int i0 = __float2int_rn(v[j].x * inv);
        int i1 = __float2int_rn(v[j].y * inv);
        int i2 = __float2int_rn(v[j].z * inv);
        int i3 = __float2int_rn(v[j].w * inv);
        dst8[lane + 32 * j] = (uint32_t)(i0 & 255) | ((uint32_t)(i1 & 255) << 8)
                            | ((uint32_t)(i2 & 255) << 16) | ((uint32_t)(i3 & 255) << 24);
    }
    if (lane == 0) { *d_scale = (mx > 0.f) ? (mx / 127.0f) : 0.f; *d_sumsq = sq; }
}

// ---------------------------------------------------------------- prep kernels
__global__ void mconv_kernel(const float* __restrict__ mem) {
    int w    = (blockIdx.x * blockDim.x + threadIdx.x) >> 5;
    int lane = threadIdx.x & 31;
    if (w >= N_MEM) return;
    quant_row((const float4*)(mem + (size_t)w * DIM),
              (uint32_t*)g_m8 + (size_t)w * 128, &g_ms[w], &g_msq[w], lane);
}

__global__ void qconv_kernel(const float* __restrict__ qm) {
    int w    = (blockIdx.x * blockDim.x + threadIdx.x) >> 5;
    int lane = threadIdx.x & 31;
    if (w >= B_Q) return;
    quant_row((const float4*)(qm + (size_t)w * DIM),
              (uint32_t*)g_q8 + (size_t)w * 128, &g_qs[w], &g_qsq[w], lane);
}

// ---------------------------------------------------------------- main kernel
// int8 IMMA approx pass; keeps top-TILE_K per query per 128-row tile.
__global__ void __launch_bounds__(256, 1) knn_imma() {
    extern __shared__ char smem[];
    const uint32_t sb = smem_u32(smem);
    const int tid  = threadIdx.x;
    const int lane = tid & 31;
    const int wid  = tid >> 5;
    const int wm   = wid >> 1;          // 0..3 : warp m-tile (64 queries)
    const int wn   = wid & 1;           // 0..1 : warp n-tile (64 rows)
    const int n0   = blockIdx.x * BN;

    // ldsm per-lane offsets (16B-half pattern; pitches chosen conflict-free)
    const uint32_t offA = (uint32_t)((wm * 64 + (lane & 15)) * APITCH + ((lane >> 4) << 4));
    const uint32_t offB = (uint32_t)((wn * 64 + (lane & 7) + ((lane >> 4) << 3)) * BPITCH
                                     + (((lane >> 3) & 1) << 4));

    int acc[4][8][4];
#pragma unroll
    for (int i = 0; i < 4; i++)
#pragma unroll
        for (int j = 0; j < 8; j++)
#pragma unroll
            for (int r = 0; r < 4; r++) acc[i][j][r] = 0;

    // ---- staging: A chunk (1024 ops, 4/thread), B chunk (512 ops, 2/thread)
    auto stageA = [&](int c) {
#pragma unroll
        for (int i = 0; i < 4; i++) {
            int idx = i * 256 + tid;            // [0,1024)
            int r = idx >> 2, j = idx & 3;
            cp16(sb + SM_A + (uint32_t)(r * APITCH + c * 64 + j * 16),
                 g_q8 + (size_t)r * DIM + (size_t)c * 64 + (size_t)j * 16);
        }
    };
    auto stageB = [&](int c) {
        uint32_t base = sb + SM_B + (c & 1) * (BN * BPITCH);
#pragma unroll
        for (int i = 0; i < 2; i++) {
            int idx = i * 256 + tid;            // [0,512)
            int r = idx >> 2, j = idx & 3;
            int grow = n0 + r;
            if (grow >= N_MEM) grow = N_MEM - 1;
            cp16(base + (uint32_t)(r * BPITCH + j * 16),
                 g_m8 + (size_t)grow * DIM + (size_t)c * 64 + (size_t)j * 16);
        }
    };

    stageA(0); stageB(0); CP_COMMIT();

    for (int c = 0; c < NCH; c++) {
        CP_WAIT0();                 // A(c), B(c) visible soon
        __syncthreads();            // everyone past MMA(c-1), staged data visible
        if (c + 1 < NCH) { stageA(c + 1); stageB(c + 1); CP_COMMIT(); }

        uint32_t bB = sb + SM_B + (c & 1) * (BN * BPITCH);
#pragma unroll
        for (int ks = 0; ks < 2; ks++) {
            const uint32_t kb = (uint32_t)(c * 64 + ks * 32);
            uint32_t Ah[4][4], Bh[8][2];
#pragma unroll
            for (int mi = 0; mi < 4; mi++)
                ldsm4(sb + SM_A + mi * 16 * APITCH + offA + kb,
                      Ah[mi][0], Ah[mi][1], Ah[mi][2], Ah[mi][3]);
#pragma unroll
            for (int jp = 0; jp < 4; jp++)
                ldsm4(bB + jp * 16 * BPITCH + offB + (uint32_t)(ks * 32),
                      Bh[jp*2][0], Bh[jp*2][1], Bh[jp*2+1][0], Bh[jp*2+1][1]);
#pragma unroll
            for (int mi = 0; mi < 4; mi++)
#pragma unroll
                for (int ni = 0; ni < 8; ni++)
                    mma_s8(acc[mi][ni], Ah[mi], Bh[ni]);
        }
    }

    // ---- load per-row msq / 2*scale for this tile ----
    {
        float* msq_s = (float*)(smem + SM_MS);
        float* tsm_s = (float*)(smem + SM_SC);
        if (tid < BN) {
            int grow = n0 + tid;
            bool v = (grow < N_MEM);
            msq_s[tid] = v ? g_msq[grow] : 3.0e38f;
            tsm_s[tid] = v ? 2.0f * g_ms[grow] : 0.f;
        }
    }
    __syncthreads();

    // ---- epilogue: int dots -> smem dist tile (pitch 129 floats, overlays A)
    float* ds = (float*)smem;
#pragma unroll
    for (int mi = 0; mi < 4; mi++) {
        int m = wm * 64 + mi * 16 + (lane >> 2);
#pragma unroll
        for (int ni = 0; ni < 8; ni++) {
            int n = wn * 64 + ni * 8 + (lane & 3) * 2;
            ds[m * 129 + n]           = (float)acc[mi][ni][0];
            ds[m * 129 + n + 1]       = (float)acc[mi][ni][1];
            ds[(m + 8) * 129 + n]     = (float)acc[mi][ni][2];
            ds[(m + 8) * 129 + n + 1] = (float)acc[mi][ni][3];
        }
    }
    __syncthreads();

    // ---- per-query approx top-TILE_K: v = msq[n] - 2*sq*sm[n]*dot ----
    {
        const float sq = g_qs[tid];
        const float* row = ds + tid * 129;
        const float* msq_s = (const float*)(smem + SM_MS);
        const float* tsm_s = (const float*)(smem + SM_SC);
        const int nvalid = (n0 + BN <= N_MEM) ? BN : (N_MEM - n0);
        float bd[TILE_K]; int bix[TILE_K];
#pragma unroll
        for (int j = 0; j < TILE_K; j++) { bd[j] = 3.0e38f; bix[j] = 0x7FFFFFFF; }
        for (int n = 0; n < nvalid; n++) {
            float dist = msq_s[n] - sq * tsm_s[n] * row[n];
            if (dist < bd[TILE_K - 1]) {
                int p = TILE_K - 1;
                while (p > 0 && bd[p - 1] > dist) {
                    bd[p] = bd[p - 1]; bix[p] = bix[p - 1]; --p;
                }
                bd[p] = dist; bix[p] = n0 + n;
            }
        }
#pragma unroll
        for (int j = 0; j < TILE_K; j++) {
            size_t o = ((size_t)tid * NTILE + blockIdx.x) * TILE_K + j;
            g_pd[o] = bd[j];
            g_pi[o] = bix[j];
        }
    }
}

// ---------------------------------------------------------------- final:
// merge approx partials -> approx top-GK -> exact fp32 rescore -> top-5
__global__ void __launch_bounds__(512) knn_final(const float* __restrict__ qm,
                                                 const float* __restrict__ mem,
                                                 float* __restrict__ out, int out_elems) {
    const int qy   = blockIdx.x;
    const int tid  = threadIdx.x;
    const int lane = tid & 31;
    const int w    = tid >> 5;
    const int CAND = NTILE * TILE_K;
    const float* pd = g_pd + (size_t)qy * CAND;
    const int*   pi = g_pi + (size_t)qy * CAND;

    __shared__ float swd[16][GK];
    __shared__ int   swi[16][GK];
    __shared__ int   cidx[GK];
    __shared__ float cd2[GK];

    // phase A: per-thread approx top-8
    const int PK = 8;
    float d[PK]; int ix[PK];
#pragma unroll
    for (int j = 0; j < PK; j++) { d[j] = 3.0e38f; ix[j] = 0x7FFFFFFF; }
    for (int c = tid; c < CAND; c += 512) {
        float dv = pd[c];
        if (dv < d[PK - 1]) {
            int di = pi[c];
            int p = PK - 1;
            while (p > 0 && (d[p-1] > dv || (d[p-1] == dv && ix[p-1] > di))) {
                d[p] = d[p-1]; ix[p] = ix[p-1]; --p;
            }
            d[p] = dv; ix[p] = di;
        }
    }

    // per-warp sorted-head merge -> sorted GK per warp
    {
        int p = 0;
#pragma unroll
        for (int r = 0; r < GK; r++) {
            float v = (p < PK) ? d[p] : 3.0e38f;
            int  id = (p < PK) ? ix[p] : 0x7FFFFFFF;
            float bv = v; int bi2 = id;
#pragma unroll
            for (int o = 16; o > 0; o >>= 1) {
                float ov = __shfl_xor_sync(0xFFFFFFFFu, bv, o);
                int   oi = __shfl_xor_sync(0xFFFFFFFFu, bi2, o);
                if (ov < bv || (ov == bv && oi < bi2)) { bv = ov; bi2 = oi; }
            }
            if (p < PK && v == bv && id == bi2) p++;
            if (lane == 0) { swd[w][r] = bv; swi[w][r] = bi2; }
        }
    }
    __syncthreads();

    // thread 0: 16-way merge of sorted lists -> approx top-GK indices
    if (tid == 0) {
        int hp[16];
#pragma unroll
        for (int i = 0; i < 16; i++) hp[i] = 0;
        for (int r = 0; r < GK; r++) {
            float bv = 3.0e38f; int bi2 = 0x7FFFFFFF, bw = -1;
            for (int i = 0; i < 16; i++) {
                if (hp[i] < GK) {
                    float v = swd[i][hp[i]]; int id = swi[i][hp[i]];
                    if (v < bv || (v == bv && id < bi2)) { bv = v; bi2 = id; bw = i; }
                }
            }
            hp[bw]++;
            cidx[r] = bi2;
        }
    }
    __syncthreads();

    // phase B: exact fp32 rescore of GK candidates (one warp per candidate)
    const float qsq = g_qsq[qy];
    const float4* qrow = (const float4*)(qm + (size_t)qy * DIM);
    for (int cc = w; cc < GK; cc += 16) {
        int row = cidx[cc];
        float dot = 0.f, ms = 0.f;
        if (row < N_MEM) {
            const float4* mrow = (const float4*)(mem + (size_t)row * DIM);
#pragma unroll
            for (int j = 0; j < 4; j++) {
                float4 qv = qrow[lane + 32 * j];
                float4 mv = mrow[lane + 32 * j];
                dot += qv.x * mv.x + qv.y * mv.y + qv.z * mv.z + qv.w * mv.w;
                ms  += mv.x * mv.x + mv.y * mv.y + mv.z * mv.z + mv.w * mv.w;
            }
        }
#pragma unroll
        for (int o = 16; o > 0; o >>= 1) {
            dot += __shfl_xor_sync(0xFFFFFFFFu, dot, o);
            ms  += __shfl_xor_sync(0xFFFFFFFFu, ms, o);
        }
        if (lane == 0)
            cd2[cc] = (row < N_MEM) ? (qsq + ms - 2.0f * dot) : 3.0e38f;
    }
    __syncthreads();

    // thread 0: exact top-5 of the GK candidates
    if (tid == 0) {
        float fd[TOPK]; int fi[TOPK];
#pragma unroll
        for (int j = 0; j < TOPK; j++) { fd[j] = 3.0e38f; fi[j] = 0x7FFFFFFF; }
        for (int c = 0; c < GK; c++) {
            float dv = cd2[c]; int di = cidx[c];
            if (dv < fd[TOPK-1] || (dv == fd[TOPK-1] && di < fi[TOPK-1])) {
                int p = TOPK - 1;
                while (p > 0 && (fd[p-1] > dv || (fd[p-1] == dv && fi[p-1] > di))) {
                    fd[p] = fd[p-1]; fi[p] = fi[p-1]; --p;
                }
                fd[p] = dv; fi[p] = di;
            }
        }
#pragma unroll
        for (int j = 0; j < TOPK; j++) {
            out[qy * TOPK + j] = fd[j];
            if (out_elems >= 2 * B_Q * TOPK)
                out[B_Q * TOPK + qy * TOPK + j] = (float)fi[j];
        }
    }
}

// ---------------------------------------------------------------- launch
extern "C" void kernel_launch(void* const* d_in, const int* in_sizes, int n_in,
                              void* d_out, int out_size) {
    const float* qm  = (const float*)d_in[0];   // query  [256, 512] f32
    const float* mem = (const float*)d_in[1];   // memory [500000, 512] f32
    (void)in_sizes; (void)n_in;

    cudaFuncSetAttribute(knn_imma, cudaFuncAttributeMaxDynamicSharedMemorySize, SMEM_BYTES);

    qconv_kernel<<<B_Q / 8, 256>>>(qm);
    mconv_kernel<<<(N_MEM + 7) / 8, 256>>>(mem);
    knn_imma<<<NTILE, 256, SMEM_BYTES>>>();
    knn_final<<<B_Q, 512>>>(qm, mem, (float*)d_out, out_size);
}

// round 11
// speedup vs baseline: 1.5636x; 1.5636x over previous
#include <cuda_runtime.h>
#include <cuda_bf16.h>
#include <cstdint>

// ---------------------------------------------------------------- constants
#define B_Q    256
#define DIM    512
#define N_MEM  500000
#define TOPK   5
#define BN     128
#define KC     64
#define NCH    8                       // 512 / 64
#define NTILE  3907                    // ceil(500000/128)
#define TILE_K 4                       // approx top-k kept per tile
#define GK     20                      // global approx candidates rescored exactly

#define FPITCH 272                     // fp32 staging row pitch (256B data + 16 pad)

// smem layout (bytes)
#define SM_A   0                       // A bf16 db: 2 * 32768 (swizzled 128B rows)
#define SM_BB  65536                   // B bf16 db: 2 * 16384 (swizzled 128B rows)
#define SM_BF  98304                   // B fp32 db: 2 * 34816 (pitch 272)
#define SM_MS  167936                  // 128 floats ||m||^2
#define SMEM_BYTES 168448
// epilogue dist tile (256*129*4 = 132096) overlays [0, 132096)

// ---------------------------------------------------------------- scratch
__device__ __align__(16) uint8_t g_qA[NCH * 32768];  // chunk-major pre-swizzled bf16 A
__device__ float g_qsq[B_Q];
__device__ float g_pd[(size_t)B_Q * NTILE * TILE_K];
__device__ int   g_pi[(size_t)B_Q * NTILE * TILE_K];

// ---------------------------------------------------------------- helpers
__device__ __forceinline__ uint32_t smem_u32(const void* p) {
    uint32_t a;
    asm("{ .reg .u64 t; cvta.to.shared.u64 t, %1; cvt.u32.u64 %0, t; }" : "=r"(a) : "l"(p));
    return a;
}
__device__ __forceinline__ uint32_t elect1() {
    uint32_t p;
    asm volatile("{\n\t.reg .pred p;\n\telect.sync _|p, 0xFFFFFFFF;\n\t"
                 "selp.b32 %0, 1, 0, p;\n\t}" : "=r"(p));
    return p;
}
__device__ __forceinline__ void cp16(uint32_t dst, const void* src) {
    asm volatile("cp.async.cg.shared.global [%0], [%1], 16;" :: "r"(dst), "l"(src));
}
#define CP_COMMIT() asm volatile("cp.async.commit_group;" ::: "memory")
#define CP_WAIT0()  asm volatile("cp.async.wait_group 0;" ::: "memory")

#define MBAR_INIT(mb, c)  asm volatile("mbarrier.init.shared.b64 [%0], %1;" :: "r"((uint32_t)(mb)), "r"((uint32_t)(c)) : "memory")
#define MBAR_EXPECT_TX(mb, b) asm volatile("mbarrier.arrive.expect_tx.shared.b64 _, [%0], %1;" :: "r"((uint32_t)(mb)), "r"((uint32_t)(b)) : "memory")
#define MBAR_WAIT(mb, ph) do {                                              \
    uint32_t _m = (uint32_t)(mb), _p = (uint32_t)(ph), _d;                  \
    asm volatile("{\n\t.reg .pred p;\n\t"                                   \
        "mbarrier.try_wait.parity.acquire.cta.shared::cta.b64 p, [%1], %2;\n\t" \
        "selp.b32 %0, 1, 0, p;\n\t}" : "=r"(_d) : "r"(_m), "r"(_p) : "memory"); \
    if (!_d) {                                                              \
        asm volatile("{\n\t.reg .pred P1;\n\t"                              \
            "WL_%=:\n\t"                                                    \
            "mbarrier.try_wait.parity.acquire.cta.shared::cta.b64 P1, [%0], %1, 0x989680;\n\t" \
            "@P1 bra.uni WD_%=;\n\t"                                        \
            "bra.uni WL_%=;\n\t"                                            \
            "WD_%=:\n\t}" :: "r"(_m), "r"(_p) : "memory");                  \
    }                                                                       \
} while (0)

__device__ __forceinline__ void bulkA(uint32_t dst, const void* src, uint32_t bytes,
                                      uint32_t mbar) {
    asm volatile("cp.async.bulk.shared::cluster.global.mbarrier::complete_tx::bytes "
                 "[%0], [%1], %2, [%3];"
                 :: "r"(dst), "l"(src), "r"(bytes), "r"(mbar) : "memory");
}

__device__ __forceinline__ void ldsm4(uint32_t a, uint32_t& r0, uint32_t& r1,
                                      uint32_t& r2, uint32_t& r3) {
    asm volatile("ldmatrix.sync.aligned.m8n8.x4.shared.b16 {%0,%1,%2,%3}, [%4];"
                 : "=r"(r0), "=r"(r1), "=r"(r2), "=r"(r3) : "r"(a));
}
__device__ __forceinline__ void mma_bf16(float* d, const uint32_t* a, const uint32_t* b) {
    asm volatile(
        "mma.sync.aligned.m16n8k16.row.col.f32.bf16.bf16.f32 "
        "{%0,%1,%2,%3}, {%4,%5,%6,%7}, {%8,%9}, {%0,%1,%2,%3};"
        : "+f"(d[0]), "+f"(d[1]), "+f"(d[2]), "+f"(d[3])
        : "r"(a[0]), "r"(a[1]), "r"(a[2]), "r"(a[3]), "r"(b[0]), "r"(b[1]));
}

// ---------------------------------------------------------------- prep kernels
// pack queries into chunk-major, pre-swizzled bf16 image for bulk copies
__global__ void qswz_kernel(const float* __restrict__ qm) {
    int g = blockIdx.x * blockDim.x + threadIdx.x;   // 16B granule id [0, 16384)
    if (g >= NCH * 2048) return;
    int c = g >> 11;                // chunk
    int r = (g >> 3) & 255;         // query row
    int j = g & 7;                  // 16B granule within 128B row
    // 8 fp32 source values
    const float4* src = (const float4*)(qm + (size_t)r * DIM + c * KC + j * 8);
    float4 v0 = src[0], v1 = src[1];
    __nv_bfloat162 h0 = __floats2bfloat162_rn(v0.x, v0.y);
    __nv_bfloat162 h1 = __floats2bfloat162_rn(v0.z, v0.w);
    __nv_bfloat162 h2 = __floats2bfloat162_rn(v1.x, v1.y);
    __nv_bfloat162 h3 = __floats2bfloat162_rn(v1.z, v1.w);
    uint4 out;
    out.x = ((uint32_t)__bfloat16_as_ushort(h0.y) << 16) | __bfloat16_as_ushort(h0.x);
    out.y = ((uint32_t)__bfloat16_as_ushort(h1.y) << 16) | __bfloat16_as_ushort(h1.x);
    out.z = ((uint32_t)__bfloat16_as_ushort(h2.y) << 16) | __bfloat16_as_ushort(h2.x);
    out.w = ((uint32_t)__bfloat16_as_ushort(h3.y) << 16) | __bfloat16_as_ushort(h3.x);
    uint32_t off = (uint32_t)(c * 32768 + r * 128 + ((j * 16) ^ ((r & 7) << 4)));
    *(uint4*)(g_qA + off) = out;
}

__global__ void qsq_kernel(const float* __restrict__ qm) {
    int w    = (blockIdx.x * blockDim.x + threadIdx.x) >> 5;
    int lane = threadIdx.x & 31;
    if (w >= B_Q) return;
    const float4* row = (const float4*)(qm + (size_t)w * DIM);
    float s = 0.f;
#pragma unroll
    for (int j = 0; j < 4; j++) {
        float4 v = row[lane + 32 * j];
        s += v.x * v.x + v.y * v.y + v.z * v.z + v.w * v.w;
    }
#pragma unroll
    for (int o = 16; o > 0; o >>= 1) s += __shfl_xor_sync(0xFFFFFFFFu, s, o);
    if (lane == 0) g_qsq[w] = s;
}

// ---------------------------------------------------------------- main kernel
// 1-term bf16 HMMA approx pass; A via cp.async.bulk, B fp32 via cp.async + convert
__global__ void __launch_bounds__(256, 1) knn_hmma(const float* __restrict__ mem) {
    extern __shared__ char smem[];
    __shared__ __align__(8) uint64_t mbar[2];
    const uint32_t sb = smem_u32(smem);
    const uint32_t mb0 = smem_u32(&mbar[0]);
    const uint32_t mb1 = smem_u32(&mbar[1]);
    const int tid  = threadIdx.x;
    const int lane = tid & 31;
    const int wid  = tid >> 5;
    const int wm   = wid >> 1;          // 0..3 : warp m-tile (64 queries)
    const int wn   = wid & 1;           // 0..1 : warp n-tile (64 rows)
    const int n0   = blockIdx.x * BN;

    // ldsm per-lane components (swizzled 128B rows, XOR addressing)
    const uint32_t rowA = (uint32_t)(wm * 64 + (lane & 15));
    const uint32_t colA = (uint32_t)((lane >> 4) << 4);
    const uint32_t xorA = (rowA & 7) << 4;
    const uint32_t rowB = (uint32_t)(wn * 64 + (lane & 7) + ((lane >> 4) << 3));
    const uint32_t colB = (uint32_t)(((lane >> 3) & 1) << 4);
    const uint32_t xorB = (rowB & 7) << 4;

    float acc[4][8][4];
#pragma unroll
    for (int i = 0; i < 4; i++)
#pragma unroll
        for (int j = 0; j < 8; j++)
#pragma unroll
            for (int r = 0; r < 4; r++) acc[i][j][r] = 0.f;

    float sqa[8];
#pragma unroll
    for (int i = 0; i < 8; i++) sqa[i] = 0.f;

    auto stageB = [&](int k) {          // B(k) fp32 -> fbuf[k&1], 8 cp16/thread
        uint32_t base = sb + SM_BF + (k & 1) * 34816;
#pragma unroll
        for (int i = 0; i < 8; i++) {
            int idx = i * 256 + tid;            // [0,2048)
            int r = idx >> 4, j = idx & 15;
            int grow = n0 + r;
            if (grow >= N_MEM) grow = N_MEM - 1;
            cp16(base + (uint32_t)(r * FPITCH + j * 16),
                 (const char*)(mem + (size_t)grow * DIM) + (size_t)k * 256 + (size_t)j * 16);
        }
    };
    auto convB = [&](int k) {           // fbuf[k&1] fp32 -> bbuf[k&1] bf16 (swizzled), + sq
        const char* f = smem + SM_BF + (k & 1) * 34816;
        char*       b = smem + SM_BB + (k & 1) * 16384;
        const int c16 = tid & 15;
        const int rb  = tid >> 4;
#pragma unroll
        for (int i = 0; i < 8; i++) {
            int r = i * 16 + rb;
            float4 v = *(const float4*)(f + r * FPITCH + c16 * 16);
            __nv_bfloat162 h0 = __floats2bfloat162_rn(v.x, v.y);
            __nv_bfloat162 h1 = __floats2bfloat162_rn(v.z, v.w);
            uint2 hu;
            hu.x = ((uint32_t)__bfloat16_as_ushort(h0.y) << 16) | __bfloat16_as_ushort(h0.x);
            hu.y = ((uint32_t)__bfloat16_as_ushort(h1.y) << 16) | __bfloat16_as_ushort(h1.x);
            *(uint2*)(b + r * 128 + ((c16 * 8) ^ ((r & 7) << 4))) = hu;
            sqa[i] += v.x * v.x + v.y * v.y + v.z * v.z + v.w * v.w;
        }
    };

    // ---- prologue ----
    if (tid == 0) { MBAR_INIT(mb0, 1); MBAR_INIT(mb1, 1); }
    stageB(0); stageB(1); CP_COMMIT();
    __syncthreads();                    // mbar init visible
    if (wid == 0 && elect1()) {
        MBAR_EXPECT_TX(mb0, 32768);
        bulkA(sb + SM_A, g_qA, 32768, mb0);
    }
    CP_WAIT0();
    __syncthreads();
    convB(0);

    // ---- main loop ----
    for (int c = 0; c < NCH; c++) {
        MBAR_WAIT((c & 1) ? mb1 : mb0, (c >> 1) & 1);   // A(c) arrived
        CP_WAIT0();                                     // B(c+1) arrived
        __syncthreads();                                // all past MMA(c-1)

        if (c + 1 < NCH) {
            if (wid == 0 && elect1()) {
                uint32_t mb = ((c + 1) & 1) ? mb1 : mb0;
                MBAR_EXPECT_TX(mb, 32768);
                bulkA(sb + SM_A + ((c + 1) & 1) * 32768,
                      g_qA + (size_t)(c + 1) * 32768, 32768, mb);
            }
            if (c + 2 < NCH) stageB(c + 2);
            CP_COMMIT();
            convB(c + 1);       // overlaps MMA(c)
        }

        uint32_t aB = sb + SM_A  + (c & 1) * 32768;
        uint32_t bB = sb + SM_BB + (c & 1) * 16384;
#pragma unroll
        for (int ks = 0; ks < 4; ks++) {
            const uint32_t ka = (uint32_t)(ks * 32);
            uint32_t Ah[4][4], Bh[8][2];
#pragma unroll
            for (int mi = 0; mi < 4; mi++) {
                uint32_t r = rowA + mi * 16;
                ldsm4(aB + r * 128 + ((ka + colA) ^ xorA),
                      Ah[mi][0], Ah[mi][1], Ah[mi][2], Ah[mi][3]);
            }
#pragma unroll
            for (int jp = 0; jp < 4; jp++) {
                uint32_t r = rowB + jp * 16;
                ldsm4(bB + r * 128 + ((ka + colB) ^ xorB),
                      Bh[jp*2][0], Bh[jp*2][1], Bh[jp*2+1][0], Bh[jp*2+1][1]);
            }
#pragma unroll
            for (int mi = 0; mi < 4; mi++)
#pragma unroll
                for (int ni = 0; ni < 8; ni++)
                    mma_bf16(acc[mi][ni], Ah[mi], Bh[ni]);
        }
    }
    __syncthreads();

    // ---- ||m||^2 reduce (across 16 c16 lanes) ----
    {
        float* msp = (float*)(smem + SM_MS);
#pragma unroll
        for (int i = 0; i < 8; i++) {
            float s = sqa[i];
            s += __shfl_xor_sync(0xFFFFFFFFu, s, 1);
            s += __shfl_xor_sync(0xFFFFFFFFu, s, 2);
            s += __shfl_xor_sync(0xFFFFFFFFu, s, 4);
            s += __shfl_xor_sync(0xFFFFFFFFu, s, 8);
            if ((lane & 15) == 0) msp[i * 16 + (tid >> 4)] = s;
        }
    }

    // ---- epilogue: dot products -> smem dist tile (pitch 129 floats) ----
    float* ds = (float*)smem;
#pragma unroll
    for (int mi = 0; mi < 4; mi++) {
        int m = wm * 64 + mi * 16 + (lane >> 2);
#pragma unroll
        for (int ni = 0; ni < 8; ni++) {
            int n = wn * 64 + ni * 8 + (lane & 3) * 2;
            ds[m * 129 + n]           = acc[mi][ni][0];
            ds[m * 129 + n + 1]       = acc[mi][ni][1];
            ds[(m + 8) * 129 + n]     = acc[mi][ni][2];
            ds[(m + 8) * 129 + n + 1] = acc[mi][ni][3];
        }
    }
    __syncthreads();

    // ---- per-query approx top-TILE_K over this CTA's 128 columns ----
    {
        const float qsq = g_qsq[tid];
        const float* row = ds + tid * 129;
        const float* msp = (const float*)(smem + SM_MS);
        const int nvalid = (n0 + BN <= N_MEM) ? BN : (N_MEM - n0);
        float bd[TILE_K]; int bix[TILE_K];
#pragma unroll
        for (int j = 0; j < TILE_K; j++) { bd[j] = 3.0e38f; bix[j] = 0x7FFFFFFF; }
        for (int n = 0; n < nvalid; n++) {
            float dist = qsq + msp[n] - 2.0f * row[n];
            if (dist < bd[TILE_K - 1]) {
                int p = TILE_K - 1;
                while (p > 0 && bd[p - 1] > dist) {
                    bd[p] = bd[p - 1]; bix[p] = bix[p - 1]; --p;
                }
                bd[p] = dist; bix[p] = n0 + n;
            }
        }
#pragma unroll
        for (int j = 0; j < TILE_K; j++) {
            size_t o = ((size_t)tid * NTILE + blockIdx.x) * TILE_K + j;
            g_pd[o] = bd[j];
            g_pi[o] = bix[j];
        }
    }
}

// ---------------------------------------------------------------- final:
// merge approx partials -> approx top-GK -> exact fp32 rescore -> top-5
__global__ void __launch_bounds__(512) knn_final(const float* __restrict__ qm,
                                                 const float* __restrict__ mem,
                                                 float* __restrict__ out, int out_elems) {
    const int qy   = blockIdx.x;
    const int tid  = threadIdx.x;
    const int lane = tid & 31;
    const int w    = tid >> 5;
    const int CAND = NTILE * TILE_K;
    const float* pd = g_pd + (size_t)qy * CAND;
    const int*   pi = g_pi + (size_t)qy * CAND;

    __shared__ float swd[16][GK];
    __shared__ int   swi[16][GK];
    __shared__ int   cidx[GK];
    __shared__ float cd2[GK];

    const int PK = 8;
    float d[PK]; int ix[PK];
#pragma unroll
    for (int j = 0; j < PK; j++) { d[j] = 3.0e38f; ix[j] = 0x7FFFFFFF; }
    for (int c = tid; c < CAND; c += 512) {
        float dv = pd[c];
        if (dv < d[PK - 1]) {
            int di = pi[c];
            int p = PK - 1;
            while (p > 0 && (d[p-1] > dv || (d[p-1] == dv && ix[p-1] > di))) {
                d[p] = d[p-1]; ix[p] = ix[p-1]; --p;
            }
            d[p] = dv; ix[p] = di;
        }
    }

    {
        int p = 0;
#pragma unroll
        for (int r = 0; r < GK; r++) {
            float v = (p < PK) ? d[p] : 3.0e38f;
            int  id = (p < PK) ? ix[p] : 0x7FFFFFFF;
            float bv = v; int bi2 = id;
#pragma unroll
            for (int o = 16; o > 0; o >>= 1) {
                float ov = __shfl_xor_sync(0xFFFFFFFFu, bv, o);
                int   oi = __shfl_xor_sync(0xFFFFFFFFu, bi2, o);
                if (ov < bv || (ov == bv && oi < bi2)) { bv = ov; bi2 = oi; }
            }
            if (p < PK && v == bv && id == bi2) p++;
            if (lane == 0) { swd[w][r] = bv; swi[w][r] = bi2; }
        }
    }
    __syncthreads();

    if (tid == 0) {
        int hp[16];
#pragma unroll
        for (int i = 0; i < 16; i++) hp[i] = 0;
        for (int r = 0; r < GK; r++) {
            float bv = 3.0e38f; int bi2 = 0x7FFFFFFF, bw = -1;
            for (int i = 0; i < 16; i++) {
                if (hp[i] < GK) {
                    float v = swd[i][hp[i]]; int id = swi[i][hp[i]];
                    if (v < bv || (v == bv && id < bi2)) { bv = v; bi2 = id; bw = i; }
                }
            }
            hp[bw]++;
            cidx[r] = bi2;
        }
    }
    __syncthreads();

    const float qsq = g_qsq[qy];
    const float4* qrow = (const float4*)(qm + (size_t)qy * DIM);
    for (int cc = w; cc < GK; cc += 16) {
        int row = cidx[cc];
        float dot = 0.f, ms = 0.f;
        if (row < N_MEM) {
            const float4* mrow = (const float4*)(mem + (size_t)row * DIM);
#pragma unroll
            for (int j = 0; j < 4; j++) {
                float4 qv = qrow[lane + 32 * j];
                float4 mv = mrow[lane + 32 * j];
                dot += qv.x * mv.x + qv.y * mv.y + qv.z * mv.z + qv.w * mv.w;
                ms  += mv.x * mv.x + mv.y * mv.y + mv.z * mv.z + mv.w * mv.w;
            }
        }
#pragma unroll
        for (int o = 16; o > 0; o >>= 1) {
            dot += __shfl_xor_sync(0xFFFFFFFFu, dot, o);
            ms  += __shfl_xor_sync(0xFFFFFFFFu, ms, o);
        }
        if (lane == 0)
            cd2[cc] = (row < N_MEM) ? (qsq + ms - 2.0f * dot) : 3.0e38f;
    }
    __syncthreads();

    if (tid == 0) {
        float fd[TOPK]; int fi[TOPK];
#pragma unroll
        for (int j = 0; j < TOPK; j++) { fd[j] = 3.0e38f; fi[j] = 0x7FFFFFFF; }
        for (int c = 0; c < GK; c++) {
            float dv = cd2[c]; int di = cidx[c];
            if (dv < fd[TOPK-1] || (dv == fd[TOPK-1] && di < fi[TOPK-1])) {
                int p = TOPK - 1;
                while (p > 0 && (fd[p-1] > dv || (fd[p-1] == dv && fi[p-1] > di))) {
                    fd[p] = fd[p-1]; fi[p] = fi[p-1]; --p;
                }
                fd[p] = dv; fi[p] = di;
            }
        }
#pragma unroll
        for (int j = 0; j < TOPK; j++) {
            out[qy * TOPK + j] = fd[j];
            if (out_elems >= 2 * B_Q * TOPK)
                out[B_Q * TOPK + qy * TOPK + j] = (float)fi[j];
        }
    }
}

// ---------------------------------------------------------------- launch
extern "C" void kernel_launch(void* const* d_in, const int* in_sizes, int n_in,
                              void* d_out, int out_size) {
    const float* qm  = (const float*)d_in[0];   // query  [256, 512] f32
    const float* mem = (const float*)d_in[1];   // memory [500000, 512] f32
    (void)in_sizes; (void)n_in;

    cudaFuncSetAttribute(knn_hmma, cudaFuncAttributeMaxDynamicSharedMemorySize, SMEM_BYTES);

    qswz_kernel<<<64, 256>>>(qm);
    qsq_kernel<<<B_Q / 8, 256>>>(qm);
    knn_hmma<<<NTILE, 256, SMEM_BYTES>>>(mem);
    knn_final<<<B_Q, 512>>>(qm, mem, (float*)d_out, out_size);
}